// round 15
// baseline (speedup 1.0000x reference)
#include <cuda_runtime.h>
#include <cuda_bf16.h>
#include <cstdint>
#include <math.h>

// ---------------- problem constants ----------------
#define BS_      16
#define LQ_      1000
#define NROWS    (BS_*LQ_)         // 16000
#define EMBED    256
#define NHEADS   8
#define HDIM     32
#define NLOGIT   384               // 256 offset cols + 128 attn-prob cols
#define LV_      13294

__device__ float g_logits[NROWS * NLOGIT];      // off(256) | softmaxed attn(128)
__device__ __nv_bfloat16 g_bhi[NLOGIT * EMBED]; // B^T split-hi [n][k]
__device__ __nv_bfloat16 g_blo[NLOGIT * EMBED]; // B^T split-lo

// ======================= helpers =======================
__device__ __forceinline__ uint32_t smem_u32(const void* p) {
    uint32_t a;
    asm("{ .reg .u64 t; cvta.to.shared.u64 t, %1; cvt.u32.u64 %0, t; }" : "=r"(a) : "l"(p));
    return a;
}

__device__ __forceinline__ void ldsm4(uint32_t& r0, uint32_t& r1, uint32_t& r2, uint32_t& r3,
                                      uint32_t addr) {
    asm volatile("ldmatrix.sync.aligned.m8n8.x4.shared.b16 {%0,%1,%2,%3}, [%4];"
                 : "=r"(r0), "=r"(r1), "=r"(r2), "=r"(r3) : "r"(addr));
}

__device__ __forceinline__ void mma16816(float* c, const uint32_t* a, const uint32_t* b) {
    asm volatile(
        "mma.sync.aligned.m16n8k16.row.col.f32.bf16.bf16.f32 "
        "{%0,%1,%2,%3}, {%4,%5,%6,%7}, {%8,%9}, {%0,%1,%2,%3};"
        : "+f"(c[0]), "+f"(c[1]), "+f"(c[2]), "+f"(c[3])
        : "r"(a[0]), "r"(a[1]), "r"(a[2]), "r"(a[3]), "r"(b[0]), "r"(b[1]));
}

__device__ __forceinline__ uint32_t pack_bf2(__nv_bfloat16 a, __nv_bfloat16 b) {
    return (uint32_t)__bfloat16_as_ushort(a) | ((uint32_t)__bfloat16_as_ushort(b) << 16);
}

// ======================= B conversion (coalesced transpose, 96 blocks) =======================
__global__ __launch_bounds__(256)
void conv_b_kernel(const float* __restrict__ Woff, const float* __restrict__ Wattn)
{
    __shared__ __nv_bfloat16 sHI[32][40];
    __shared__ __nv_bfloat16 sLO[32][40];

    const int nb = blockIdx.x;              // 0..11
    const int kb = blockIdx.y;              // 0..7
    const int nx = threadIdx.x & 31;
    const int ky = threadIdx.x >> 5;        // 0..7
    const int n  = nb * 32 + nx;
    const bool attn = (n >= 256);
    const float* src  = attn ? (Wattn + (n - 256)) : (Woff + n);
    const int    lds_ = attn ? 128 : 256;

    #pragma unroll
    for (int i = 0; i < 4; i++) {
        const int kl = i * 8 + ky;
        const float x = __ldg(src + (size_t)(kb * 32 + kl) * lds_);
        const __nv_bfloat16 h = __float2bfloat16(x);
        sHI[nx][kl] = h;
        sLO[nx][kl] = __float2bfloat16(x - __bfloat162float(h));
    }
    __syncthreads();

    if (threadIdx.x < 128) {
        const int n2 = threadIdx.x >> 2;    // 0..31
        const int v  = threadIdx.x & 3;     // 0..3
        const int kl = v * 8;
        const int gn = nb * 32 + n2;
        const int gk = kb * 32 + kl;
        const __nv_bfloat16* ph = &sHI[n2][kl];
        const __nv_bfloat16* pl = &sLO[n2][kl];
        uint4 uh, ul;
        uh.x = pack_bf2(ph[0], ph[1]); uh.y = pack_bf2(ph[2], ph[3]);
        uh.z = pack_bf2(ph[4], ph[5]); uh.w = pack_bf2(ph[6], ph[7]);
        ul.x = pack_bf2(pl[0], pl[1]); ul.y = pack_bf2(pl[2], pl[3]);
        ul.z = pack_bf2(pl[4], pl[5]); ul.w = pack_bf2(pl[6], pl[7]);
        *reinterpret_cast<uint4*>(g_bhi + (size_t)gn * EMBED + gk) = uh;
        *reinterpret_cast<uint4*>(g_blo + (size_t)gn * EMBED + gk) = ul;
    }
}

// ======================= mma.sync GEMM (R13 config + row_base for chunking) =======================
#define LDA    72
#define A_HI   0
#define A_LO   9216                 // 64*72*2
#define B_HI   18432
#define B_LO   36864
#define SMT    55296
#define LDD    132

__global__ __launch_bounds__(256, 4)
void mma_gemm_kernel(const float* __restrict__ Q,
                     const float* __restrict__ boff, const float* __restrict__ battn,
                     int row_base)
{
    extern __shared__ char smem[];
    const int tid  = threadIdx.x;
    const int wid  = tid >> 5;
    const int lane = tid & 31;
    const int bn   = blockIdx.y;
    const int rowg = row_base + blockIdx.x * 64;
    const uint32_t sb = smem_u32(smem);

    const int warp_m = (wid >> 1) * 16;
    const int warp_n = (wid & 1) * 64;

    float acc[8][4];
    #pragma unroll
    for (int nj = 0; nj < 8; nj++)
        #pragma unroll
        for (int c = 0; c < 4; c++) acc[nj][c] = 0.f;

    for (int kc = 0; kc < 4; kc++) {
        const int k0 = kc * 64;
        __syncthreads();

        #pragma unroll
        for (int r = 0; r < 2; r++) {
            const int s = tid + r * 256;
            const int row = s >> 3, j = s & 7;
            const uint32_t doff = (uint32_t)(row * LDA + j * 8) * 2;
            const float* asrc = Q + (size_t)(rowg + row) * EMBED + k0 + j * 8;
            const float4 a0 = __ldg(reinterpret_cast<const float4*>(asrc));
            const float4 a1 = __ldg(reinterpret_cast<const float4*>(asrc) + 1);
            const float av[8] = {a0.x, a0.y, a0.z, a0.w, a1.x, a1.y, a1.z, a1.w};
            __nv_bfloat16 hi[8], lo[8];
            #pragma unroll
            for (int t = 0; t < 8; t++) {
                hi[t] = __float2bfloat16(av[t]);
                lo[t] = __float2bfloat16(av[t] - __bfloat162float(hi[t]));
            }
            uint4 uh, ul;
            uh.x = pack_bf2(hi[0], hi[1]); uh.y = pack_bf2(hi[2], hi[3]);
            uh.z = pack_bf2(hi[4], hi[5]); uh.w = pack_bf2(hi[6], hi[7]);
            ul.x = pack_bf2(lo[0], lo[1]); ul.y = pack_bf2(lo[2], lo[3]);
            ul.z = pack_bf2(lo[4], lo[5]); ul.w = pack_bf2(lo[6], lo[7]);
            *reinterpret_cast<uint4*>(smem + A_HI + doff) = uh;
            *reinterpret_cast<uint4*>(smem + A_LO + doff) = ul;
        }
        #pragma unroll
        for (int r = 0; r < 4; r++) {
            const int s = tid + r * 256;
            const int row = s >> 3, j = s & 7;
            const uint32_t doff = (uint32_t)(row * LDA + j * 8) * 2;
            const size_t bsrc = (size_t)(bn * 128 + row) * EMBED + k0 + j * 8;
            *reinterpret_cast<uint4*>(smem + B_HI + doff) = *reinterpret_cast<const uint4*>(g_bhi + bsrc);
            *reinterpret_cast<uint4*>(smem + B_LO + doff) = *reinterpret_cast<const uint4*>(g_blo + bsrc);
        }
        __syncthreads();

        #pragma unroll
        for (int ks = 0; ks < 4; ks++) {
            const int kk = ks * 16;

            uint32_t ah[4], al[4];
            const int ar = warp_m + (lane & 15);
            const int ac = kk + ((lane >> 4) << 3);
            const uint32_t ad = sb + A_HI + (uint32_t)((ar * LDA + ac) << 1);
            ldsm4(ah[0], ah[1], ah[2], ah[3], ad);
            ldsm4(al[0], al[1], al[2], al[3], ad + (A_LO - A_HI));

            const int br = warp_n + (lane & 7) + ((lane >> 4) << 3);
            const int bc = kk + (((lane >> 3) & 1) << 3);
            #pragma unroll
            for (int g = 0; g < 4; g++) {
                uint32_t bh[4], bl[4];
                const uint32_t bd = sb + B_HI + (uint32_t)(((br + g * 16) * LDA + bc) << 1);
                ldsm4(bh[0], bh[1], bh[2], bh[3], bd);
                ldsm4(bl[0], bl[1], bl[2], bl[3], bd + (B_LO - B_HI));

                mma16816(acc[g * 2],     ah, &bh[0]);
                mma16816(acc[g * 2],     ah, &bl[0]);
                mma16816(acc[g * 2],     al, &bh[0]);
                mma16816(acc[g * 2 + 1], ah, &bh[2]);
                mma16816(acc[g * 2 + 1], ah, &bl[2]);
                mma16816(acc[g * 2 + 1], al, &bh[2]);
            }
        }
    }

    __syncthreads();
    float* sD = reinterpret_cast<float*>(smem);
    #pragma unroll
    for (int nj = 0; nj < 8; nj++) {
        const int r0 = warp_m + (lane >> 2);
        const int c0 = warp_n + nj * 8 + (lane & 3) * 2;
        *reinterpret_cast<float2*>(sD + r0 * LDD + c0)       = make_float2(acc[nj][0], acc[nj][1]);
        *reinterpret_cast<float2*>(sD + (r0 + 8) * LDD + c0) = make_float2(acc[nj][2], acc[nj][3]);
    }
    __syncthreads();

    const int row = tid >> 2;              // 0..63
    const int cs  = (tid & 3) * 32;
    float* orow = g_logits + (size_t)(rowg + row) * NLOGIT + bn * 128 + cs;

    float f[32];
    #pragma unroll
    for (int j = 0; j < 32; j++) {
        const int c = cs + j;
        const float bias = (bn < 2) ? __ldg(boff + bn * 128 + c) : __ldg(battn + c);
        f[j] = sD[row * LDD + c] + bias;
    }
    if (bn == 2) {
        #pragma unroll
        for (int g = 0; g < 2; g++) {
            float mx = f[g * 16];
            #pragma unroll
            for (int j = 1; j < 16; j++) mx = fmaxf(mx, f[g * 16 + j]);
            float s = 0.f;
            #pragma unroll
            for (int j = 0; j < 16; j++) { f[g * 16 + j] = __expf(f[g * 16 + j] - mx); s += f[g * 16 + j]; }
            const float rs = __fdividef(1.f, s);
            #pragma unroll
            for (int j = 0; j < 16; j++) f[g * 16 + j] *= rs;
        }
    }
    #pragma unroll
    for (int j = 0; j < 32; j += 4)
        *reinterpret_cast<float4*>(orow + j) = make_float4(f[j], f[j+1], f[j+2], f[j+3]);
}

// ======================= sampling kernel (row-major warp mapping for chunking) =======================
// warp = row*8 + h : one block = one row's 8 heads (logits/refp row reused in L1).
// Inner structure identical to the frozen R7 local optimum.
__global__ __launch_bounds__(256, 6)
void sample_kernel(const float* __restrict__ value,
                   const float* __restrict__ refp,
                   float* __restrict__ out,
                   int row_base)
{
    constexpr int cW[4]  = {100, 50, 25, 13};
    constexpr int cVS[4] = {0, 10000, 12500, 13125};

    const int warp = (row_base << 3) + (blockIdx.x << 3) + (threadIdx.x >> 5);
    const int lane = threadIdx.x & 31;

    const int row = warp >> 3;
    const int h   = warp & 7;
    const int b   = row / LQ_;

    const float* lg = g_logits + (size_t)row * NLOGIT;
    const float4 rp = __ldg(reinterpret_cast<const float4*>(refp) + row);

    const int psub = lane >> 3;
    const int dgrp = lane & 7;

    const float2* offp = reinterpret_cast<const float2*>(lg) + h * 16 + psub;
    const float*  app  = lg + 256 + h * 16 + psub;

    float2 off[4];
    float  ap[4];
    #pragma unroll
    for (int it = 0; it < 4; it++) {
        off[it] = __ldg(offp + (it << 2));
        ap[it]  = __ldg(app  + (it << 2));
    }

    const float* vb = value + (size_t)b * LV_ * EMBED + h * HDIM + dgrp * 4;

    float4 acc0 = make_float4(0.f, 0.f, 0.f, 0.f);
    float4 acc1 = acc0;

    #pragma unroll
    for (int it = 0; it < 4; it++) {
        const int   W  = cW[it];
        const float Wf = (float)W;

        const float px = fmaf(fmaf(off[it].x, 0.125f * rp.z, rp.x), Wf, -0.5f);
        const float py = fmaf(fmaf(off[it].y, 0.125f * rp.w, rp.y), Wf, -0.5f);
        const float fx0 = floorf(px), fy0 = floorf(py);
        const float fx = px - fx0,    fy = py - fy0;
        const int x0 = (int)fx0, y0 = (int)fy0;

        const float gx = 1.f - fx, gy = 1.f - fy;
        const float w00 = ap[it] * gx * gy;
        const float w10 = ap[it] * fx * gy;
        const float w01 = ap[it] * gx * fy;
        const float w11 = ap[it] * fx * fy;

        const bool xin0 = (unsigned)x0       < (unsigned)W;
        const bool xin1 = (unsigned)(x0 + 1) < (unsigned)W;
        const bool yin0 = (unsigned)y0       < (unsigned)W;   // H == W
        const bool yin1 = (unsigned)(y0 + 1) < (unsigned)W;

        const float* vl = vb + (ptrdiff_t)cVS[it] * EMBED
                             + (ptrdiff_t)(y0 * W + x0) * EMBED;

        float4 v00 = make_float4(0.f,0.f,0.f,0.f);
        float4 v10 = v00, v01 = v00, v11 = v00;
        if (xin0 && yin0) v00 = *reinterpret_cast<const float4*>(vl);
        if (xin1 && yin0) v10 = *reinterpret_cast<const float4*>(vl + EMBED);
        if (xin0 && yin1) v01 = *reinterpret_cast<const float4*>(vl + W * EMBED);
        if (xin1 && yin1) v11 = *reinterpret_cast<const float4*>(vl + W * EMBED + EMBED);

        float4& acc = (it & 1) ? acc1 : acc0;
        acc.x = fmaf(w00, v00.x, fmaf(w10, v10.x, fmaf(w01, v01.x, fmaf(w11, v11.x, acc.x))));
        acc.y = fmaf(w00, v00.y, fmaf(w10, v10.y, fmaf(w01, v01.y, fmaf(w11, v11.y, acc.y))));
        acc.z = fmaf(w00, v00.z, fmaf(w10, v10.z, fmaf(w01, v01.z, fmaf(w11, v11.z, acc.z))));
        acc.w = fmaf(w00, v00.w, fmaf(w10, v10.w, fmaf(w01, v01.w, fmaf(w11, v11.w, acc.w))));
    }

    float4 acc;
    acc.x = acc0.x + acc1.x;
    acc.y = acc0.y + acc1.y;
    acc.z = acc0.z + acc1.z;
    acc.w = acc0.w + acc1.w;

    #pragma unroll
    for (int o = 8; o <= 16; o <<= 1) {
        acc.x += __shfl_xor_sync(0xffffffffu, acc.x, o);
        acc.y += __shfl_xor_sync(0xffffffffu, acc.y, o);
        acc.z += __shfl_xor_sync(0xffffffffu, acc.z, o);
        acc.w += __shfl_xor_sync(0xffffffffu, acc.w, o);
    }

    if (psub == 0) {
        *reinterpret_cast<float4*>(out + (size_t)row * EMBED + h * HDIM + dgrp * 4) = acc;
    }
}

// ---------------- launch: 4-chunk fork-join pipeline ----------------
extern "C" void kernel_launch(void* const* d_in, const int* in_sizes, int n_in,
                              void* d_out, int out_size)
{
    (void)in_sizes; (void)n_in; (void)out_size;
    const float* query = (const float*)d_in[0];
    const float* refp  = (const float*)d_in[1];
    const float* value = (const float*)d_in[2];
    // d_in[3] = value_spatial_shapes (int64) — hardcoded
    const float* Woff  = (const float*)d_in[4];
    const float* boff  = (const float*)d_in[5];
    const float* Wattn = (const float*)d_in[6];
    const float* battn = (const float*)d_in[7];
    float* out = (float*)d_out;

    static bool init_done = false;
    static cudaStream_t s1;
    static cudaEvent_t evm[4], evj;
    if (!init_done) {
        cudaFuncSetAttribute(mma_gemm_kernel,
                             cudaFuncAttributeMaxDynamicSharedMemorySize, SMT);
        cudaStreamCreateWithFlags(&s1, cudaStreamNonBlocking);
        for (int p = 0; p < 4; p++)
            cudaEventCreateWithFlags(&evm[p], cudaEventDisableTiming);
        cudaEventCreateWithFlags(&evj, cudaEventDisableTiming);
        init_done = true;
    }

    // row chunks (multiples of 64): 4096, 4096, 4096, 3712
    const int rbase[4]  = {0, 4096, 8192, 12288};
    const int rcount[4] = {4096, 4096, 4096, 3712};

    conv_b_kernel<<<dim3(NLOGIT / 32, 8), 256>>>(Woff, Wattn);

    for (int p = 0; p < 4; p++) {
        mma_gemm_kernel<<<dim3(rcount[p] / 64, 3), 256, SMT>>>(query, boff, battn, rbase[p]);
        cudaEventRecord(evm[p], 0);
        cudaStreamWaitEvent(s1, evm[p], 0);
        sample_kernel<<<rcount[p], 256, 0, s1>>>(value, refp, out, rbase[p]);
    }
    cudaEventRecord(evj, s1);
    cudaStreamWaitEvent(0, evj, 0);
}

// round 16
// speedup vs baseline: 1.6821x; 1.6821x over previous
#include <cuda_runtime.h>
#include <cuda_bf16.h>
#include <cstdint>
#include <math.h>

// ---------------- problem constants ----------------
#define BS_      16
#define LQ_      1000
#define NROWS    (BS_*LQ_)         // 16000
#define EMBED    256
#define NHEADS   8
#define HDIM     32
#define NLOGIT   384               // 256 offset cols + 128 attn-prob cols
#define LV_      13294

__device__ float g_logits[NROWS * NLOGIT];      // off(256) | softmaxed attn(128)
__device__ __nv_bfloat16 g_bhi[NLOGIT * EMBED]; // B^T split-hi [n][k]
__device__ __nv_bfloat16 g_blo[NLOGIT * EMBED]; // B^T split-lo

// ======================= helpers =======================
__device__ __forceinline__ uint32_t smem_u32(const void* p) {
    uint32_t a;
    asm("{ .reg .u64 t; cvta.to.shared.u64 t, %1; cvt.u32.u64 %0, t; }" : "=r"(a) : "l"(p));
    return a;
}

__device__ __forceinline__ void ldsm4(uint32_t& r0, uint32_t& r1, uint32_t& r2, uint32_t& r3,
                                      uint32_t addr) {
    asm volatile("ldmatrix.sync.aligned.m8n8.x4.shared.b16 {%0,%1,%2,%3}, [%4];"
                 : "=r"(r0), "=r"(r1), "=r"(r2), "=r"(r3) : "r"(addr));
}

__device__ __forceinline__ void mma16816(float* c, const uint32_t* a, const uint32_t* b) {
    asm volatile(
        "mma.sync.aligned.m16n8k16.row.col.f32.bf16.bf16.f32 "
        "{%0,%1,%2,%3}, {%4,%5,%6,%7}, {%8,%9}, {%0,%1,%2,%3};"
        : "+f"(c[0]), "+f"(c[1]), "+f"(c[2]), "+f"(c[3])
        : "r"(a[0]), "r"(a[1]), "r"(a[2]), "r"(a[3]), "r"(b[0]), "r"(b[1]));
}

__device__ __forceinline__ uint32_t pack_bf2(__nv_bfloat16 a, __nv_bfloat16 b) {
    return (uint32_t)__bfloat16_as_ushort(a) | ((uint32_t)__bfloat16_as_ushort(b) << 16);
}

// ======================= B conversion (coalesced transpose, 96 blocks) =======================
__global__ __launch_bounds__(256)
void conv_b_kernel(const float* __restrict__ Woff, const float* __restrict__ Wattn)
{
    __shared__ __nv_bfloat16 sHI[32][40];
    __shared__ __nv_bfloat16 sLO[32][40];

    const int nb = blockIdx.x;              // 0..11
    const int kb = blockIdx.y;              // 0..7
    const int nx = threadIdx.x & 31;
    const int ky = threadIdx.x >> 5;        // 0..7
    const int n  = nb * 32 + nx;
    const bool attn = (n >= 256);
    const float* src  = attn ? (Wattn + (n - 256)) : (Woff + n);
    const int    lds_ = attn ? 128 : 256;

    #pragma unroll
    for (int i = 0; i < 4; i++) {
        const int kl = i * 8 + ky;
        const float x = __ldg(src + (size_t)(kb * 32 + kl) * lds_);
        const __nv_bfloat16 h = __float2bfloat16(x);
        sHI[nx][kl] = h;
        sLO[nx][kl] = __float2bfloat16(x - __bfloat162float(h));
    }
    __syncthreads();

    if (threadIdx.x < 128) {
        const int n2 = threadIdx.x >> 2;    // 0..31
        const int v  = threadIdx.x & 3;     // 0..3
        const int kl = v * 8;
        const int gn = nb * 32 + n2;
        const int gk = kb * 32 + kl;
        const __nv_bfloat16* ph = &sHI[n2][kl];
        const __nv_bfloat16* pl = &sLO[n2][kl];
        uint4 uh, ul;
        uh.x = pack_bf2(ph[0], ph[1]); uh.y = pack_bf2(ph[2], ph[3]);
        uh.z = pack_bf2(ph[4], ph[5]); uh.w = pack_bf2(ph[6], ph[7]);
        ul.x = pack_bf2(pl[0], pl[1]); ul.y = pack_bf2(pl[2], pl[3]);
        ul.z = pack_bf2(pl[4], pl[5]); ul.w = pack_bf2(pl[6], pl[7]);
        *reinterpret_cast<uint4*>(g_bhi + (size_t)gn * EMBED + gk) = uh;
        *reinterpret_cast<uint4*>(g_blo + (size_t)gn * EMBED + gk) = ul;
    }
}

// ======================= mma.sync GEMM (R13 champion config) =======================
#define LDA    72
#define A_HI   0
#define A_LO   9216                 // 64*72*2
#define B_HI   18432
#define B_LO   36864
#define SMT    55296
#define LDD    132

__global__ __launch_bounds__(256, 4)
void mma_gemm_kernel(const float* __restrict__ Q,
                     const float* __restrict__ boff, const float* __restrict__ battn)
{
    extern __shared__ char smem[];
    const int tid  = threadIdx.x;
    const int wid  = tid >> 5;
    const int lane = tid & 31;
    const int bn   = blockIdx.y;
    const int rowg = blockIdx.x * 64;
    const uint32_t sb = smem_u32(smem);

    const int warp_m = (wid >> 1) * 16;
    const int warp_n = (wid & 1) * 64;

    float acc[8][4];
    #pragma unroll
    for (int nj = 0; nj < 8; nj++)
        #pragma unroll
        for (int c = 0; c < 4; c++) acc[nj][c] = 0.f;

    for (int kc = 0; kc < 4; kc++) {
        const int k0 = kc * 64;
        __syncthreads();

        #pragma unroll
        for (int r = 0; r < 2; r++) {
            const int s = tid + r * 256;
            const int row = s >> 3, j = s & 7;
            const uint32_t doff = (uint32_t)(row * LDA + j * 8) * 2;
            const float* asrc = Q + (size_t)(rowg + row) * EMBED + k0 + j * 8;
            const float4 a0 = __ldg(reinterpret_cast<const float4*>(asrc));
            const float4 a1 = __ldg(reinterpret_cast<const float4*>(asrc) + 1);
            const float av[8] = {a0.x, a0.y, a0.z, a0.w, a1.x, a1.y, a1.z, a1.w};
            __nv_bfloat16 hi[8], lo[8];
            #pragma unroll
            for (int t = 0; t < 8; t++) {
                hi[t] = __float2bfloat16(av[t]);
                lo[t] = __float2bfloat16(av[t] - __bfloat162float(hi[t]));
            }
            uint4 uh, ul;
            uh.x = pack_bf2(hi[0], hi[1]); uh.y = pack_bf2(hi[2], hi[3]);
            uh.z = pack_bf2(hi[4], hi[5]); uh.w = pack_bf2(hi[6], hi[7]);
            ul.x = pack_bf2(lo[0], lo[1]); ul.y = pack_bf2(lo[2], lo[3]);
            ul.z = pack_bf2(lo[4], lo[5]); ul.w = pack_bf2(lo[6], lo[7]);
            *reinterpret_cast<uint4*>(smem + A_HI + doff) = uh;
            *reinterpret_cast<uint4*>(smem + A_LO + doff) = ul;
        }
        #pragma unroll
        for (int r = 0; r < 4; r++) {
            const int s = tid + r * 256;
            const int row = s >> 3, j = s & 7;
            const uint32_t doff = (uint32_t)(row * LDA + j * 8) * 2;
            const size_t bsrc = (size_t)(bn * 128 + row) * EMBED + k0 + j * 8;
            *reinterpret_cast<uint4*>(smem + B_HI + doff) = *reinterpret_cast<const uint4*>(g_bhi + bsrc);
            *reinterpret_cast<uint4*>(smem + B_LO + doff) = *reinterpret_cast<const uint4*>(g_blo + bsrc);
        }
        __syncthreads();

        #pragma unroll
        for (int ks = 0; ks < 4; ks++) {
            const int kk = ks * 16;

            uint32_t ah[4], al[4];
            const int ar = warp_m + (lane & 15);
            const int ac = kk + ((lane >> 4) << 3);
            const uint32_t ad = sb + A_HI + (uint32_t)((ar * LDA + ac) << 1);
            ldsm4(ah[0], ah[1], ah[2], ah[3], ad);
            ldsm4(al[0], al[1], al[2], al[3], ad + (A_LO - A_HI));

            const int br = warp_n + (lane & 7) + ((lane >> 4) << 3);
            const int bc = kk + (((lane >> 3) & 1) << 3);
            #pragma unroll
            for (int g = 0; g < 4; g++) {
                uint32_t bh[4], bl[4];
                const uint32_t bd = sb + B_HI + (uint32_t)(((br + g * 16) * LDA + bc) << 1);
                ldsm4(bh[0], bh[1], bh[2], bh[3], bd);
                ldsm4(bl[0], bl[1], bl[2], bl[3], bd + (B_LO - B_HI));

                mma16816(acc[g * 2],     ah, &bh[0]);
                mma16816(acc[g * 2],     ah, &bl[0]);
                mma16816(acc[g * 2],     al, &bh[0]);
                mma16816(acc[g * 2 + 1], ah, &bh[2]);
                mma16816(acc[g * 2 + 1], ah, &bl[2]);
                mma16816(acc[g * 2 + 1], al, &bh[2]);
            }
        }
    }

    __syncthreads();
    float* sD = reinterpret_cast<float*>(smem);
    #pragma unroll
    for (int nj = 0; nj < 8; nj++) {
        const int r0 = warp_m + (lane >> 2);
        const int c0 = warp_n + nj * 8 + (lane & 3) * 2;
        *reinterpret_cast<float2*>(sD + r0 * LDD + c0)       = make_float2(acc[nj][0], acc[nj][1]);
        *reinterpret_cast<float2*>(sD + (r0 + 8) * LDD + c0) = make_float2(acc[nj][2], acc[nj][3]);
    }
    __syncthreads();

    const int row = tid >> 2;              // 0..63
    const int cs  = (tid & 3) * 32;
    float* orow = g_logits + (size_t)(rowg + row) * NLOGIT + bn * 128 + cs;

    float f[32];
    #pragma unroll
    for (int j = 0; j < 32; j++) {
        const int c = cs + j;
        const float bias = (bn < 2) ? __ldg(boff + bn * 128 + c) : __ldg(battn + c);
        f[j] = sD[row * LDD + c] + bias;
    }
    if (bn == 2) {
        #pragma unroll
        for (int g = 0; g < 2; g++) {
            float mx = f[g * 16];
            #pragma unroll
            for (int j = 1; j < 16; j++) mx = fmaxf(mx, f[g * 16 + j]);
            float s = 0.f;
            #pragma unroll
            for (int j = 0; j < 16; j++) { f[g * 16 + j] = __expf(f[g * 16 + j] - mx); s += f[g * 16 + j]; }
            const float rs = __fdividef(1.f, s);
            #pragma unroll
            for (int j = 0; j < 16; j++) f[g * 16 + j] *= rs;
        }
    }
    #pragma unroll
    for (int j = 0; j < 32; j += 4)
        *reinterpret_cast<float4*>(orow + j) = make_float4(f[j], f[j+1], f[j+2], f[j+3]);
}

// ======================= sampling kernel (R7 structure, full-occupancy cap) =======================
// One warp per (b, h, q); lean shuffle-free gather. __launch_bounds__(256, 8)
// targets 64 warps/SM to saturate the L1/LSU pipe (8.2M-wavefront floor ~28us;
// at 48 warps we ran 73us with issue=53% — underfed LSU).
__global__ __launch_bounds__(256, 8)
void sample_kernel(const float* __restrict__ value,
                   const float* __restrict__ refp,
                   float* __restrict__ out)
{
    constexpr int cW[4]  = {100, 50, 25, 13};
    constexpr int cVS[4] = {0, 10000, 12500, 13125};

    const int warp = (blockIdx.x << 3) + (threadIdx.x >> 5);
    const int lane = threadIdx.x & 31;

    const int q  = warp % LQ_;
    const int bh = warp / LQ_;
    const int b  = bh >> 3;
    const int h  = bh & 7;
    const int row = b * LQ_ + q;

    const float* lg = g_logits + (size_t)row * NLOGIT;
    const float4 rp = __ldg(reinterpret_cast<const float4*>(refp) + row);

    const int psub = lane >> 3;
    const int dgrp = lane & 7;

    const float2* offp = reinterpret_cast<const float2*>(lg) + h * 16 + psub;
    const float*  app  = lg + 256 + h * 16 + psub;

    float2 off[4];
    float  ap[4];
    #pragma unroll
    for (int it = 0; it < 4; it++) {
        off[it] = __ldg(offp + (it << 2));
        ap[it]  = __ldg(app  + (it << 2));
    }

    const float* vb = value + (size_t)b * LV_ * EMBED + h * HDIM + dgrp * 4;

    float4 acc0 = make_float4(0.f, 0.f, 0.f, 0.f);
    float4 acc1 = acc0;

    #pragma unroll
    for (int it = 0; it < 4; it++) {
        const int   W  = cW[it];
        const float Wf = (float)W;

        const float px = fmaf(fmaf(off[it].x, 0.125f * rp.z, rp.x), Wf, -0.5f);
        const float py = fmaf(fmaf(off[it].y, 0.125f * rp.w, rp.y), Wf, -0.5f);
        const float fx0 = floorf(px), fy0 = floorf(py);
        const float fx = px - fx0,    fy = py - fy0;
        const int x0 = (int)fx0, y0 = (int)fy0;

        const float gx = 1.f - fx, gy = 1.f - fy;
        const float w00 = ap[it] * gx * gy;
        const float w10 = ap[it] * fx * gy;
        const float w01 = ap[it] * gx * fy;
        const float w11 = ap[it] * fx * fy;

        const bool xin0 = (unsigned)x0       < (unsigned)W;
        const bool xin1 = (unsigned)(x0 + 1) < (unsigned)W;
        const bool yin0 = (unsigned)y0       < (unsigned)W;   // H == W
        const bool yin1 = (unsigned)(y0 + 1) < (unsigned)W;

        const float* vl = vb + (ptrdiff_t)cVS[it] * EMBED
                             + (ptrdiff_t)(y0 * W + x0) * EMBED;

        float4 v00 = make_float4(0.f,0.f,0.f,0.f);
        float4 v10 = v00, v01 = v00, v11 = v00;
        if (xin0 && yin0) v00 = *reinterpret_cast<const float4*>(vl);
        if (xin1 && yin0) v10 = *reinterpret_cast<const float4*>(vl + EMBED);
        if (xin0 && yin1) v01 = *reinterpret_cast<const float4*>(vl + W * EMBED);
        if (xin1 && yin1) v11 = *reinterpret_cast<const float4*>(vl + W * EMBED + EMBED);

        float4& acc = (it & 1) ? acc1 : acc0;
        acc.x = fmaf(w00, v00.x, fmaf(w10, v10.x, fmaf(w01, v01.x, fmaf(w11, v11.x, acc.x))));
        acc.y = fmaf(w00, v00.y, fmaf(w10, v10.y, fmaf(w01, v01.y, fmaf(w11, v11.y, acc.y))));
        acc.z = fmaf(w00, v00.z, fmaf(w10, v10.z, fmaf(w01, v01.z, fmaf(w11, v11.z, acc.z))));
        acc.w = fmaf(w00, v00.w, fmaf(w10, v10.w, fmaf(w01, v01.w, fmaf(w11, v11.w, acc.w))));
    }

    float4 acc;
    acc.x = acc0.x + acc1.x;
    acc.y = acc0.y + acc1.y;
    acc.z = acc0.z + acc1.z;
    acc.w = acc0.w + acc1.w;

    #pragma unroll
    for (int o = 8; o <= 16; o <<= 1) {
        acc.x += __shfl_xor_sync(0xffffffffu, acc.x, o);
        acc.y += __shfl_xor_sync(0xffffffffu, acc.y, o);
        acc.z += __shfl_xor_sync(0xffffffffu, acc.z, o);
        acc.w += __shfl_xor_sync(0xffffffffu, acc.w, o);
    }

    if (psub == 0) {
        *reinterpret_cast<float4*>(out + (size_t)row * EMBED + h * HDIM + dgrp * 4) = acc;
    }
}

// ---------------- launch (serial — R13 champion structure) ----------------
extern "C" void kernel_launch(void* const* d_in, const int* in_sizes, int n_in,
                              void* d_out, int out_size)
{
    (void)in_sizes; (void)n_in; (void)out_size;
    const float* query = (const float*)d_in[0];
    const float* refp  = (const float*)d_in[1];
    const float* value = (const float*)d_in[2];
    // d_in[3] = value_spatial_shapes (int64) — hardcoded
    const float* Woff  = (const float*)d_in[4];
    const float* boff  = (const float*)d_in[5];
    const float* Wattn = (const float*)d_in[6];
    const float* battn = (const float*)d_in[7];
    float* out = (float*)d_out;

    static bool attr_set = false;
    if (!attr_set) {
        cudaFuncSetAttribute(mma_gemm_kernel,
                             cudaFuncAttributeMaxDynamicSharedMemorySize, SMT);
        attr_set = true;
    }

    conv_b_kernel<<<dim3(NLOGIT / 32, 8), 256>>>(Woff, Wattn);
    mma_gemm_kernel<<<dim3(NROWS / 64, 3), 256, SMT>>>(query, boff, battn);
    sample_kernel<<<(BS_ * NHEADS * LQ_) / 8, 256>>>(value, refp, out);
}

// round 17
// speedup vs baseline: 1.7078x; 1.0153x over previous
#include <cuda_runtime.h>
#include <cuda_bf16.h>
#include <cstdint>
#include <math.h>

// ---------------- problem constants ----------------
#define BS_      16
#define LQ_      1000
#define NROWS    (BS_*LQ_)         // 16000
#define EMBED    256
#define NHEADS   8
#define HDIM     32
#define NLOGIT   384               // 256 offset cols + 128 attn-prob cols
#define LV_      13294

__device__ float g_logits[NROWS * NLOGIT];      // off(256) | softmaxed attn(128)
__device__ __nv_bfloat16 g_bhi[NLOGIT * EMBED]; // B^T split-hi [n][k]
__device__ __nv_bfloat16 g_blo[NLOGIT * EMBED]; // B^T split-lo

// ======================= helpers =======================
__device__ __forceinline__ uint32_t smem_u32(const void* p) {
    uint32_t a;
    asm("{ .reg .u64 t; cvta.to.shared.u64 t, %1; cvt.u32.u64 %0, t; }" : "=r"(a) : "l"(p));
    return a;
}

__device__ __forceinline__ void ldsm4(uint32_t& r0, uint32_t& r1, uint32_t& r2, uint32_t& r3,
                                      uint32_t addr) {
    asm volatile("ldmatrix.sync.aligned.m8n8.x4.shared.b16 {%0,%1,%2,%3}, [%4];"
                 : "=r"(r0), "=r"(r1), "=r"(r2), "=r"(r3) : "r"(addr));
}

__device__ __forceinline__ void mma16816(float* c, const uint32_t* a, const uint32_t* b) {
    asm volatile(
        "mma.sync.aligned.m16n8k16.row.col.f32.bf16.bf16.f32 "
        "{%0,%1,%2,%3}, {%4,%5,%6,%7}, {%8,%9}, {%0,%1,%2,%3};"
        : "+f"(c[0]), "+f"(c[1]), "+f"(c[2]), "+f"(c[3])
        : "r"(a[0]), "r"(a[1]), "r"(a[2]), "r"(a[3]), "r"(b[0]), "r"(b[1]));
}

__device__ __forceinline__ uint32_t pack_bf2(__nv_bfloat16 a, __nv_bfloat16 b) {
    return (uint32_t)__bfloat16_as_ushort(a) | ((uint32_t)__bfloat16_as_ushort(b) << 16);
}

// ======================= B conversion (coalesced transpose, 96 blocks) =======================
__global__ __launch_bounds__(256)
void conv_b_kernel(const float* __restrict__ Woff, const float* __restrict__ Wattn)
{
    __shared__ __nv_bfloat16 sHI[32][40];
    __shared__ __nv_bfloat16 sLO[32][40];

    const int nb = blockIdx.x;              // 0..11
    const int kb = blockIdx.y;              // 0..7
    const int nx = threadIdx.x & 31;
    const int ky = threadIdx.x >> 5;        // 0..7
    const int n  = nb * 32 + nx;
    const bool attn = (n >= 256);
    const float* src  = attn ? (Wattn + (n - 256)) : (Woff + n);
    const int    lds_ = attn ? 128 : 256;

    #pragma unroll
    for (int i = 0; i < 4; i++) {
        const int kl = i * 8 + ky;
        const float x = __ldg(src + (size_t)(kb * 32 + kl) * lds_);
        const __nv_bfloat16 h = __float2bfloat16(x);
        sHI[nx][kl] = h;
        sLO[nx][kl] = __float2bfloat16(x - __bfloat162float(h));
    }
    __syncthreads();

    if (threadIdx.x < 128) {
        const int n2 = threadIdx.x >> 2;    // 0..31
        const int v  = threadIdx.x & 3;     // 0..3
        const int kl = v * 8;
        const int gn = nb * 32 + n2;
        const int gk = kb * 32 + kl;
        const __nv_bfloat16* ph = &sHI[n2][kl];
        const __nv_bfloat16* pl = &sLO[n2][kl];
        uint4 uh, ul;
        uh.x = pack_bf2(ph[0], ph[1]); uh.y = pack_bf2(ph[2], ph[3]);
        uh.z = pack_bf2(ph[4], ph[5]); uh.w = pack_bf2(ph[6], ph[7]);
        ul.x = pack_bf2(pl[0], pl[1]); ul.y = pack_bf2(pl[2], pl[3]);
        ul.z = pack_bf2(pl[4], pl[5]); ul.w = pack_bf2(pl[6], pl[7]);
        *reinterpret_cast<uint4*>(g_bhi + (size_t)gn * EMBED + gk) = uh;
        *reinterpret_cast<uint4*>(g_blo + (size_t)gn * EMBED + gk) = ul;
    }
}

// ======================= mma.sync GEMM (K chunked 2 x 128 — fewer sync phases) =======================
// C[16000,384] = Q @ [W_off|W_attn]^T via split-bf16 (Ah*Bh + Ah*Bl + Al*Bh), fp32 acc.
// grid (250, 3): CTA tile 64(M) x 128(N), 8 warps, warp tile 16x64.
// K = 256 in 2 chunks of 128: halves the stage->sync->compute phase count vs
// the 4x64 chunking (isolating the sync-overhead axis; prefetch and occupancy
// were shown neutral in R12/R13). smem 104.4 KB -> 2 CTAs/SM.
#define LDA    136                 // bf16 elems per smem row (128 + 8 pad)
#define A_HI   0
#define A_LO   17408               // 64*136*2
#define B_HI   34816
#define B_LO   69632               // +128*136*2
#define SMT    104448
#define LDD    132

__global__ __launch_bounds__(256, 2)
void mma_gemm_kernel(const float* __restrict__ Q,
                     const float* __restrict__ boff, const float* __restrict__ battn)
{
    extern __shared__ char smem[];
    const int tid  = threadIdx.x;
    const int wid  = tid >> 5;
    const int lane = tid & 31;
    const int bn   = blockIdx.y;
    const int rowg = blockIdx.x * 64;
    const uint32_t sb = smem_u32(smem);

    const int warp_m = (wid >> 1) * 16;
    const int warp_n = (wid & 1) * 64;

    float acc[8][4];
    #pragma unroll
    for (int nj = 0; nj < 8; nj++)
        #pragma unroll
        for (int c = 0; c < 4; c++) acc[nj][c] = 0.f;

    for (int kc = 0; kc < 2; kc++) {
        const int k0 = kc * 128;
        __syncthreads();

        // --- A: 64 rows x 128 k, fp32 -> bf16 hi/lo in-register ---
        #pragma unroll
        for (int r = 0; r < 4; r++) {
            const int s = tid + r * 256;        // 0..1023
            const int row = s >> 4, j = s & 15;
            const uint32_t doff = (uint32_t)(row * LDA + j * 8) * 2;
            const float* asrc = Q + (size_t)(rowg + row) * EMBED + k0 + j * 8;
            const float4 a0 = __ldg(reinterpret_cast<const float4*>(asrc));
            const float4 a1 = __ldg(reinterpret_cast<const float4*>(asrc) + 1);
            const float av[8] = {a0.x, a0.y, a0.z, a0.w, a1.x, a1.y, a1.z, a1.w};
            __nv_bfloat16 hi[8], lo[8];
            #pragma unroll
            for (int t = 0; t < 8; t++) {
                hi[t] = __float2bfloat16(av[t]);
                lo[t] = __float2bfloat16(av[t] - __bfloat162float(hi[t]));
            }
            uint4 uh, ul;
            uh.x = pack_bf2(hi[0], hi[1]); uh.y = pack_bf2(hi[2], hi[3]);
            uh.z = pack_bf2(hi[4], hi[5]); uh.w = pack_bf2(hi[6], hi[7]);
            ul.x = pack_bf2(lo[0], lo[1]); ul.y = pack_bf2(lo[2], lo[3]);
            ul.z = pack_bf2(lo[4], lo[5]); ul.w = pack_bf2(lo[6], lo[7]);
            *reinterpret_cast<uint4*>(smem + A_HI + doff) = uh;
            *reinterpret_cast<uint4*>(smem + A_LO + doff) = ul;
        }
        // --- B: 128 n-rows x 128 k, pre-split bf16 ---
        #pragma unroll
        for (int r = 0; r < 8; r++) {
            const int s = tid + r * 256;        // 0..2047
            const int row = s >> 4, j = s & 15;
            const uint32_t doff = (uint32_t)(row * LDA + j * 8) * 2;
            const size_t bsrc = (size_t)(bn * 128 + row) * EMBED + k0 + j * 8;
            *reinterpret_cast<uint4*>(smem + B_HI + doff) = *reinterpret_cast<const uint4*>(g_bhi + bsrc);
            *reinterpret_cast<uint4*>(smem + B_LO + doff) = *reinterpret_cast<const uint4*>(g_blo + bsrc);
        }
        __syncthreads();

        #pragma unroll
        for (int ks = 0; ks < 8; ks++) {
            const int kk = ks * 16;

            uint32_t ah[4], al[4];
            const int ar = warp_m + (lane & 15);
            const int ac = kk + ((lane >> 4) << 3);
            const uint32_t ad = sb + A_HI + (uint32_t)((ar * LDA + ac) << 1);
            ldsm4(ah[0], ah[1], ah[2], ah[3], ad);
            ldsm4(al[0], al[1], al[2], al[3], ad + (A_LO - A_HI));

            const int br = warp_n + (lane & 7) + ((lane >> 4) << 3);
            const int bc = kk + (((lane >> 3) & 1) << 3);
            #pragma unroll
            for (int g = 0; g < 4; g++) {
                uint32_t bh[4], bl[4];
                const uint32_t bd = sb + B_HI + (uint32_t)(((br + g * 16) * LDA + bc) << 1);
                ldsm4(bh[0], bh[1], bh[2], bh[3], bd);
                ldsm4(bl[0], bl[1], bl[2], bl[3], bd + (B_LO - B_HI));

                mma16816(acc[g * 2],     ah, &bh[0]);
                mma16816(acc[g * 2],     ah, &bl[0]);
                mma16816(acc[g * 2],     al, &bh[0]);
                mma16816(acc[g * 2 + 1], ah, &bh[2]);
                mma16816(acc[g * 2 + 1], ah, &bl[2]);
                mma16816(acc[g * 2 + 1], al, &bh[2]);
            }
        }
    }

    // ---- accumulators -> reused smem D tile [64][LDD] ----
    __syncthreads();
    float* sD = reinterpret_cast<float*>(smem);
    #pragma unroll
    for (int nj = 0; nj < 8; nj++) {
        const int r0 = warp_m + (lane >> 2);
        const int c0 = warp_n + nj * 8 + (lane & 3) * 2;
        *reinterpret_cast<float2*>(sD + r0 * LDD + c0)       = make_float2(acc[nj][0], acc[nj][1]);
        *reinterpret_cast<float2*>(sD + (r0 + 8) * LDD + c0) = make_float2(acc[nj][2], acc[nj][3]);
    }
    __syncthreads();

    // ---- epilogue: bias (+softmax for attn block) -> g_logits ----
    const int row = tid >> 2;              // 0..63
    const int cs  = (tid & 3) * 32;
    float* orow = g_logits + (size_t)(rowg + row) * NLOGIT + bn * 128 + cs;

    float f[32];
    #pragma unroll
    for (int j = 0; j < 32; j++) {
        const int c = cs + j;
        const float bias = (bn < 2) ? __ldg(boff + bn * 128 + c) : __ldg(battn + c);
        f[j] = sD[row * LDD + c] + bias;
    }
    if (bn == 2) {
        #pragma unroll
        for (int g = 0; g < 2; g++) {
            float mx = f[g * 16];
            #pragma unroll
            for (int j = 1; j < 16; j++) mx = fmaxf(mx, f[g * 16 + j]);
            float s = 0.f;
            #pragma unroll
            for (int j = 0; j < 16; j++) { f[g * 16 + j] = __expf(f[g * 16 + j] - mx); s += f[g * 16 + j]; }
            const float rs = __fdividef(1.f, s);
            #pragma unroll
            for (int j = 0; j < 16; j++) f[g * 16 + j] *= rs;
        }
    }
    #pragma unroll
    for (int j = 0; j < 32; j += 4)
        *reinterpret_cast<float4*>(orow + j) = make_float4(f[j], f[j+1], f[j+2], f[j+3]);
}

// ======================= sampling kernel (R7/R13 champion config — frozen) =======================
__global__ __launch_bounds__(256, 6)
void sample_kernel(const float* __restrict__ value,
                   const float* __restrict__ refp,
                   float* __restrict__ out)
{
    constexpr int cW[4]  = {100, 50, 25, 13};
    constexpr int cVS[4] = {0, 10000, 12500, 13125};

    const int warp = (blockIdx.x << 3) + (threadIdx.x >> 5);
    const int lane = threadIdx.x & 31;

    const int q  = warp % LQ_;
    const int bh = warp / LQ_;
    const int b  = bh >> 3;
    const int h  = bh & 7;
    const int row = b * LQ_ + q;

    const float* lg = g_logits + (size_t)row * NLOGIT;
    const float4 rp = __ldg(reinterpret_cast<const float4*>(refp) + row);

    const int psub = lane >> 3;
    const int dgrp = lane & 7;

    const float2* offp = reinterpret_cast<const float2*>(lg) + h * 16 + psub;
    const float*  app  = lg + 256 + h * 16 + psub;

    float2 off[4];
    float  ap[4];
    #pragma unroll
    for (int it = 0; it < 4; it++) {
        off[it] = __ldg(offp + (it << 2));
        ap[it]  = __ldg(app  + (it << 2));
    }

    const float* vb = value + (size_t)b * LV_ * EMBED + h * HDIM + dgrp * 4;

    float4 acc0 = make_float4(0.f, 0.f, 0.f, 0.f);
    float4 acc1 = acc0;

    #pragma unroll
    for (int it = 0; it < 4; it++) {
        const int   W  = cW[it];
        const float Wf = (float)W;

        const float px = fmaf(fmaf(off[it].x, 0.125f * rp.z, rp.x), Wf, -0.5f);
        const float py = fmaf(fmaf(off[it].y, 0.125f * rp.w, rp.y), Wf, -0.5f);
        const float fx0 = floorf(px), fy0 = floorf(py);
        const float fx = px - fx0,    fy = py - fy0;
        const int x0 = (int)fx0, y0 = (int)fy0;

        const float gx = 1.f - fx, gy = 1.f - fy;
        const float w00 = ap[it] * gx * gy;
        const float w10 = ap[it] * fx * gy;
        const float w01 = ap[it] * gx * fy;
        const float w11 = ap[it] * fx * fy;

        const bool xin0 = (unsigned)x0       < (unsigned)W;
        const bool xin1 = (unsigned)(x0 + 1) < (unsigned)W;
        const bool yin0 = (unsigned)y0       < (unsigned)W;   // H == W
        const bool yin1 = (unsigned)(y0 + 1) < (unsigned)W;

        const float* vl = vb + (ptrdiff_t)cVS[it] * EMBED
                             + (ptrdiff_t)(y0 * W + x0) * EMBED;

        float4 v00 = make_float4(0.f,0.f,0.f,0.f);
        float4 v10 = v00, v01 = v00, v11 = v00;
        if (xin0 && yin0) v00 = *reinterpret_cast<const float4*>(vl);
        if (xin1 && yin0) v10 = *reinterpret_cast<const float4*>(vl + EMBED);
        if (xin0 && yin1) v01 = *reinterpret_cast<const float4*>(vl + W * EMBED);
        if (xin1 && yin1) v11 = *reinterpret_cast<const float4*>(vl + W * EMBED + EMBED);

        float4& acc = (it & 1) ? acc1 : acc0;
        acc.x = fmaf(w00, v00.x, fmaf(w10, v10.x, fmaf(w01, v01.x, fmaf(w11, v11.x, acc.x))));
        acc.y = fmaf(w00, v00.y, fmaf(w10, v10.y, fmaf(w01, v01.y, fmaf(w11, v11.y, acc.y))));
        acc.z = fmaf(w00, v00.z, fmaf(w10, v10.z, fmaf(w01, v01.z, fmaf(w11, v11.z, acc.z))));
        acc.w = fmaf(w00, v00.w, fmaf(w10, v10.w, fmaf(w01, v01.w, fmaf(w11, v11.w, acc.w))));
    }

    float4 acc;
    acc.x = acc0.x + acc1.x;
    acc.y = acc0.y + acc1.y;
    acc.z = acc0.z + acc1.z;
    acc.w = acc0.w + acc1.w;

    #pragma unroll
    for (int o = 8; o <= 16; o <<= 1) {
        acc.x += __shfl_xor_sync(0xffffffffu, acc.x, o);
        acc.y += __shfl_xor_sync(0xffffffffu, acc.y, o);
        acc.z += __shfl_xor_sync(0xffffffffu, acc.z, o);
        acc.w += __shfl_xor_sync(0xffffffffu, acc.w, o);
    }

    if (psub == 0) {
        *reinterpret_cast<float4*>(out + (size_t)row * EMBED + h * HDIM + dgrp * 4) = acc;
    }
}

// ---------------- launch ----------------
extern "C" void kernel_launch(void* const* d_in, const int* in_sizes, int n_in,
                              void* d_out, int out_size)
{
    (void)in_sizes; (void)n_in; (void)out_size;
    const float* query = (const float*)d_in[0];
    const float* refp  = (const float*)d_in[1];
    const float* value = (const float*)d_in[2];
    // d_in[3] = value_spatial_shapes (int64) — hardcoded
    const float* Woff  = (const float*)d_in[4];
    const float* boff  = (const float*)d_in[5];
    const float* Wattn = (const float*)d_in[6];
    const float* battn = (const float*)d_in[7];
    float* out = (float*)d_out;

    static bool attr_set = false;
    if (!attr_set) {
        cudaFuncSetAttribute(mma_gemm_kernel,
                             cudaFuncAttributeMaxDynamicSharedMemorySize, SMT);
        attr_set = true;
    }

    conv_b_kernel<<<dim3(NLOGIT / 32, 8), 256>>>(Woff, Wattn);
    mma_gemm_kernel<<<dim3(NROWS / 64, 3), 256, SMT>>>(query, boff, battn);
    sample_kernel<<<(BS_ * NHEADS * LQ_) / 8, 256>>>(value, refp, out);
}